// round 6
// baseline (speedup 1.0000x reference)
#include <cuda_runtime.h>
#include <cstdint>

#define V 8192
#define NB 64
#define M3 24576
#define STRIDE 8194
#define MT 128
#define NTILE 192          // 24576 / 128 m-tiles
#define KS 8               // split-K factor
#define NUNITS (NTILE * KS)          // 1536
#define GRID 148           // persistent, 1 CTA/SM
#define KC 32
#define SPU 32             // stages per unit: 1024 K / 32
#define NST 4              // cp.async ring depth

#define PC 136             // C tile pitch (floats): 136%32=8 -> conflict-free
#define PF 72
#define PD 72

#define CS_FLOATS (KC * PC)                  // 4352
#define FS_FLOATS (KC * PF)                  // 2304
#define SB_FLOATS (CS_FLOATS + FS_FLOATS)    // 6656
#define SB_BYTES  (SB_FLOATS * 4)
#define DS_OFF    (NST * SB_FLOATS)          // floats
#define SOUT_OFF  (DS_OFF + MT * PD)
#define SMEM_DYN  ((SOUT_OFF + 192) * 4)     // ~144 KB

#define MMA_TF32(d, a0, a1, a2, a3, b0, b1)                                   \
    asm volatile("mma.sync.aligned.m16n8k8.row.col.f32.tf32.tf32.f32 "        \
        "{%0,%1,%2,%3}, {%4,%5,%6,%7}, {%8,%9}, {%0,%1,%2,%3};"               \
        : "+f"((d)[0]), "+f"((d)[1]), "+f"((d)[2]), "+f"((d)[3])              \
        : "r"(a0), "r"(a1), "r"(a2), "r"(a3), "r"(b0), "r"(b1))

#define CP16(dst_u32, src_gl) \
    asm volatile("cp.async.cg.shared.global [%0], [%1], 16;" :: "r"(dst_u32), "l"(src_gl))
#define CP_COMMIT()  asm volatile("cp.async.commit_group;" ::: "memory")
#define CP_WAIT2()   asm volatile("cp.async.wait_group 2;" ::: "memory")

__device__ float g_fT[V * NB];   // 2 MB, L2-resident: f transposed [i][b], tf32-rounded

__device__ __forceinline__ float rn_tf32(float x) {
    return __uint_as_float(__float_as_uint(x) + 0x1000u);
}
__device__ __forceinline__ unsigned fbits_rn(float x) { return __float_as_uint(x) + 0x1000u; }
__device__ __forceinline__ unsigned fbits(float x)    { return __float_as_uint(x); }

// ---------------------------------------------------------------------------
__global__ void prep_kernel(const float* __restrict__ func, float* __restrict__ out) {
    int idx = blockIdx.x * 256 + threadIdx.x;    // < V*NB
    int i = idx >> 6;
    int b = idx & 63;
    g_fT[idx] = rn_tf32(func[b * STRIDE + i]);
    if (idx < NB) {
        const float QI = 1000000000.0f;
        float a1 = func[idx * STRIDE + V];
        float a2 = func[idx * STRIDE + V + 1];
        out[idx * 3 + 0] = a1 * -QI;
        out[idx * 3 + 1] = (1.0f - (1.0f - a1) * (1.0f - a2)) * -QI;
        out[idx * 3 + 2] = 0.0f;
    }
}

// ---------------------------------------------------------------------------
// Persistent tf32 mma.sync GEMM over (m-tile x k-slice) units.
// ---------------------------------------------------------------------------
__global__ __launch_bounds__(256, 1)
void cooc_mma(const float* __restrict__ cooc,
              const float* __restrict__ arg,
              float* __restrict__ out) {
    extern __shared__ float sm[];
    float* Ds   = sm + DS_OFF;
    float* sout = sm + SOUT_OFF;

    const int tid  = threadIdx.x;
    const int lane = tid & 31;
    const int wid  = tid >> 5;
    const int mg   = wid & 3;
    const int kg   = wid >> 2;
    const int quad = lane & 3;
    const int qid  = lane >> 2;
    const int bid  = blockIdx.x;

    const int nu    = 1 + (NUNITS - 1 - bid) / GRID;
    const int total = nu << 5;

    unsigned smem_base;
    asm("{ .reg .u64 t; cvta.to.shared.u64 t, %1; cvt.u32.u64 %0, t; }"
        : "=r"(smem_base) : "l"(sm));

    int crow[4], cc16[4];
    #pragma unroll
    for (int it = 0; it < 4; it++) {
        int flat = it * 256 + tid;
        crow[it] = flat >> 5;
        cc16[it] = flat & 31;
    }
    int frow[2], fc16[2];
    #pragma unroll
    for (int it = 0; it < 2; it++) {
        int flat = it * 256 + tid;
        frow[it] = flat >> 4;
        fc16[it] = flat & 15;
    }

    const char* cooc_g = (const char*)__cvta_generic_to_global(cooc);
    const char* fT_g   = (const char*)__cvta_generic_to_global(g_fT);

    auto issue = [&](int g) {
        int ui = g >> 5, sl = g & 31;
        int u  = bid + ui * GRID;
        int ks = u / NTILE;
        int tile = u - ks * NTILE;
        int m0 = tile * MT;
        int k0 = ks * (V / KS) + sl * KC;
        unsigned buf = smem_base + (unsigned)(g & (NST - 1)) * SB_BYTES;
        #pragma unroll
        for (int it = 0; it < 4; it++) {
            const char* src = cooc_g + ((size_t)(k0 + crow[it]) * M3 + m0 + cc16[it] * 4) * 4;
            CP16(buf + (unsigned)(crow[it] * PC + cc16[it] * 4) * 4, src);
        }
        unsigned fb = buf + CS_FLOATS * 4;
        #pragma unroll
        for (int it = 0; it < 2; it++) {
            const char* src = fT_g + ((size_t)(k0 + frow[it]) * NB + fc16[it] * 4) * 4;
            CP16(fb + (unsigned)(frow[it] * PF + fc16[it] * 4) * 4, src);
        }
    };

    float acc[2][8][4];
    #pragma unroll
    for (int mt = 0; mt < 2; mt++)
        #pragma unroll
        for (int nt = 0; nt < 8; nt++)
            #pragma unroll
            for (int r = 0; r < 4; r++) acc[mt][nt][r] = 0.0f;

    float po0 = 0.f, po1 = 0.f, po2 = 0.f;
    const int bb = tid & 63;
    const int mq = tid >> 6;
    const float* argb = arg + bb * STRIDE;

    issue(0); CP_COMMIT();
    issue(1); CP_COMMIT();
    issue(2); CP_COMMIT();

    for (int g = 0; g < total; g++) {
        CP_WAIT2();
        __syncthreads();

        if (g + 3 < total) issue(g + 3);
        CP_COMMIT();

        // ---- compute stage g from ring buffer ----
        const float* buf = sm + (g & (NST - 1)) * SB_FLOATS;
        const float* csA = buf + quad * PC + mg * 32 + qid;
        const float* fsB = buf + CS_FLOATS + quad * PF + qid;

        #pragma unroll
        for (int kk = 0; kk < 2; kk++) {
            const int kb = kg * 16 + kk * 8;
            const float* ca = csA + kb * PC;
            const float* fb = fsB + kb * PF;
            unsigned b0[8], b1[8];
            #pragma unroll
            for (int nt = 0; nt < 8; nt++) {
                b0[nt] = fbits(fb[nt * 8]);
                b1[nt] = fbits(fb[4 * PF + nt * 8]);
            }
            #pragma unroll
            for (int mt = 0; mt < 2; mt++) {
                unsigned a0 = fbits_rn(ca[mt * 16]);
                unsigned a1 = fbits_rn(ca[mt * 16 + 8]);
                unsigned a2 = fbits_rn(ca[4 * PC + mt * 16]);
                unsigned a3 = fbits_rn(ca[4 * PC + mt * 16 + 8]);
                #pragma unroll
                for (int nt = 0; nt < 8; nt++)
                    MMA_TF32(acc[mt][nt], a0, a1, a2, a3, b0[nt], b1[nt]);
            }
        }

        // ---- unit boundary: fold accumulators into per-(b,k) register partials ----
        if ((g & (SPU - 1)) == SPU - 1) {
            __syncthreads();                    // all warps done with this unit's MMAs
            if (kg == 0) {
                #pragma unroll
                for (int mt = 0; mt < 2; mt++) {
                    int ml = mg * 32 + mt * 16 + qid;
                    #pragma unroll
                    for (int nt = 0; nt < 8; nt++) {
                        int bc = nt * 8 + 2 * quad;
                        Ds[ml * PD + bc]           = acc[mt][nt][0];
                        Ds[ml * PD + bc + 1]       = acc[mt][nt][1];
                        Ds[(ml + 8) * PD + bc]     = acc[mt][nt][2];
                        Ds[(ml + 8) * PD + bc + 1] = acc[mt][nt][3];
                    }
                }
            }
            __syncthreads();
            if (kg == 1) {
                #pragma unroll
                for (int mt = 0; mt < 2; mt++) {
                    int ml = mg * 32 + mt * 16 + qid;
                    #pragma unroll
                    for (int nt = 0; nt < 8; nt++) {
                        int bc = nt * 8 + 2 * quad;
                        Ds[ml * PD + bc]           += acc[mt][nt][0];
                        Ds[ml * PD + bc + 1]       += acc[mt][nt][1];
                        Ds[(ml + 8) * PD + bc]     += acc[mt][nt][2];
                        Ds[(ml + 8) * PD + bc + 1] += acc[mt][nt][3];
                    }
                }
            }
            __syncthreads();

            // column reduction for this unit's tile -> register partials
            {
                int u  = bid + (g >> 5) * GRID;
                int ks = u / NTILE;
                int m0 = (u - ks * NTILE) * MT;
                #pragma unroll 4
                for (int mm = 0; mm < 32; mm++) {
                    int ml = mq * 32 + mm;
                    int m = m0 + ml;
                    unsigned j = (unsigned)m / 3u;
                    int k = m - 3 * (int)j;
                    float t = Ds[ml * PD + bb] * __ldg(argb + j);
                    if (k == 0) po0 += t;
                    else if (k == 1) po1 += t;
                    else po2 += t;
                }
            }
            __syncthreads();                    // Ds free for next unit

            #pragma unroll
            for (int mt = 0; mt < 2; mt++)
                #pragma unroll
                for (int nt = 0; nt < 8; nt++)
                    #pragma unroll
                    for (int r = 0; r < 4; r++) acc[mt][nt][r] = 0.0f;
        }
    }

    // ---- final flush: one pass of shared + global atomics ----
    if (tid < 192) sout[tid] = 0.0f;
    __syncthreads();
    atomicAdd(&sout[bb * 3 + 0], po0);
    atomicAdd(&sout[bb * 3 + 1], po1);
    atomicAdd(&sout[bb * 3 + 2], po2);
    __syncthreads();
    if (tid < 192) atomicAdd(&out[tid], sout[tid]);
}

// ---------------------------------------------------------------------------
extern "C" void kernel_launch(void* const* d_in, const int* in_sizes, int n_in,
                              void* d_out, int out_size) {
    const float* func = (const float*)d_in[0];
    const float* arg  = (const float*)d_in[1];
    const float* cooc = (const float*)d_in[2];
    float* out = (float*)d_out;

    cudaFuncSetAttribute(cooc_mma, cudaFuncAttributeMaxDynamicSharedMemorySize, SMEM_DYN);

    prep_kernel<<<(V * NB) / 256, 256>>>(func, out);
    cooc_mma<<<GRID, 256, SMEM_DYN>>>(cooc, arg, out);
}

// round 7
// speedup vs baseline: 1.2341x; 1.2341x over previous
#include <cuda_runtime.h>
#include <cstdint>

#define V 8192
#define NB 64
#define M3 24576
#define STRIDE 8194
#define MT 128
#define NTILE 192            // 24576 / 128 m-tiles
#define KS 16                // split-K factor -> 512 K per unit
#define NUNITS (NTILE * KS)  // 3072
#define GRID 296             // persistent, 2 CTAs/SM
#define KC 32
#define SPU 16               // stages per unit (512/32)
#define NST 3                // cp.async ring depth

#define PC 136               // C tile pitch (floats): conflict-free frag reads
#define PF 72
#define PD 72

#define CS_FLOATS (KC * PC)                  // 4352
#define FS_FLOATS (KC * PF)                  // 2304
#define SB_FLOATS (CS_FLOATS + FS_FLOATS)    // 6656
#define SB_BYTES  (SB_FLOATS * 4)
#define DS_OFF    (NST * SB_FLOATS)          // 19968 floats
#define SOUT_OFF  (DS_OFF + 64 * PD)         // 24576
#define SMEM_DYN  ((SOUT_OFF + 192) * 4)     // 99072 B -> 2 CTAs/SM

#define MMA_TF32(d, a0, a1, a2, a3, b0, b1)                                   \
    asm volatile("mma.sync.aligned.m16n8k8.row.col.f32.tf32.tf32.f32 "        \
        "{%0,%1,%2,%3}, {%4,%5,%6,%7}, {%8,%9}, {%0,%1,%2,%3};"               \
        : "+f"((d)[0]), "+f"((d)[1]), "+f"((d)[2]), "+f"((d)[3])              \
        : "r"(a0), "r"(a1), "r"(a2), "r"(a3), "r"(b0), "r"(b1))

#define CP16(dst_u32, src_gl) \
    asm volatile("cp.async.cg.shared.global [%0], [%1], 16;" :: "r"(dst_u32), "l"(src_gl))
#define CP_COMMIT()  asm volatile("cp.async.commit_group;" ::: "memory")
#define CP_WAIT1()   asm volatile("cp.async.wait_group 1;" ::: "memory")

__device__ float g_fT[V * NB];   // 2 MB, L2-resident: f transposed [i][b], tf32-rounded

__device__ __forceinline__ float rn_tf32(float x) {
    return __uint_as_float(__float_as_uint(x) + 0x1000u);
}
__device__ __forceinline__ unsigned fbits_rn(float x) { return __float_as_uint(x) + 0x1000u; }
__device__ __forceinline__ unsigned fbits(float x)    { return __float_as_uint(x); }

// ---------------------------------------------------------------------------
__global__ void prep_kernel(const float* __restrict__ func, float* __restrict__ out) {
    int idx = blockIdx.x * 256 + threadIdx.x;    // < V*NB
    int i = idx >> 6;
    int b = idx & 63;
    g_fT[idx] = rn_tf32(func[b * STRIDE + i]);
    if (idx < NB) {
        const float QI = 1000000000.0f;
        float a1 = func[idx * STRIDE + V];
        float a2 = func[idx * STRIDE + V + 1];
        out[idx * 3 + 0] = a1 * -QI;
        out[idx * 3 + 1] = (1.0f - (1.0f - a1) * (1.0f - a2)) * -QI;
        out[idx * 3 + 2] = 0.0f;
    }
}

// ---------------------------------------------------------------------------
// Persistent tf32 mma.sync GEMM, 2 CTAs/SM, units = 128m x 512K.
// ---------------------------------------------------------------------------
__global__ __launch_bounds__(256, 2)
void cooc_mma(const float* __restrict__ cooc,
              const float* __restrict__ arg,
              float* __restrict__ out) {
    extern __shared__ float sm[];
    float* Ds   = sm + DS_OFF;      // 64 x PD (one mt-slab at a time)
    float* sout = sm + SOUT_OFF;

    const int tid  = threadIdx.x;
    const int lane = tid & 31;
    const int wid  = tid >> 5;
    const int mg   = wid & 3;
    const int kg   = wid >> 2;
    const int quad = lane & 3;
    const int qid  = lane >> 2;
    const int bid  = blockIdx.x;

    const int nu    = 1 + (NUNITS - 1 - bid) / GRID;
    const int total = nu * SPU;

    unsigned smem_base;
    asm("{ .reg .u64 t; cvta.to.shared.u64 t, %1; cvt.u32.u64 %0, t; }"
        : "=r"(smem_base) : "l"(sm));

    int crow[4], cc16[4];
    #pragma unroll
    for (int it = 0; it < 4; it++) {
        int flat = it * 256 + tid;
        crow[it] = flat >> 5;
        cc16[it] = flat & 31;
    }
    int frow[2], fc16[2];
    #pragma unroll
    for (int it = 0; it < 2; it++) {
        int flat = it * 256 + tid;
        frow[it] = flat >> 4;
        fc16[it] = flat & 15;
    }

    const char* cooc_g = (const char*)__cvta_generic_to_global(cooc);
    const char* fT_g   = (const char*)__cvta_generic_to_global(g_fT);

    auto issue = [&](int g) {
        int ui = g >> 4, sl = g & 15;
        int u  = bid + ui * GRID;
        int ks = u / NTILE;
        int tile = u - ks * NTILE;
        int m0 = tile * MT;
        int k0 = ks * (V / KS) + sl * KC;
        unsigned buf = smem_base + (unsigned)((g % NST) * SB_BYTES);
        #pragma unroll
        for (int it = 0; it < 4; it++) {
            const char* src = cooc_g + ((size_t)(k0 + crow[it]) * M3 + m0 + cc16[it] * 4) * 4;
            CP16(buf + (unsigned)(crow[it] * PC + cc16[it] * 4) * 4, src);
        }
        unsigned fb = buf + CS_FLOATS * 4;
        #pragma unroll
        for (int it = 0; it < 2; it++) {
            const char* src = fT_g + ((size_t)(k0 + frow[it]) * NB + fc16[it] * 4) * 4;
            CP16(fb + (unsigned)(frow[it] * PF + fc16[it] * 4) * 4, src);
        }
    };

    float acc[2][8][4];
    #pragma unroll
    for (int mt = 0; mt < 2; mt++)
        #pragma unroll
        for (int nt = 0; nt < 8; nt++)
            #pragma unroll
            for (int r = 0; r < 4; r++) acc[mt][nt][r] = 0.0f;

    float po0 = 0.f, po1 = 0.f, po2 = 0.f;
    const int bb = tid & 63;
    const int mq = tid >> 6;
    const float* argb = arg + bb * STRIDE;

    issue(0); CP_COMMIT();
    issue(1); CP_COMMIT();

    for (int g = 0; g < total; g++) {
        CP_WAIT1();
        __syncthreads();

        if (g + 2 < total) issue(g + 2);
        CP_COMMIT();

        // ---- compute stage g ----
        const float* buf = sm + (g % NST) * SB_FLOATS;
        const float* csA = buf + quad * PC + mg * 32 + qid;
        const float* fsB = buf + CS_FLOATS + quad * PF + qid;

        #pragma unroll
        for (int kk = 0; kk < 2; kk++) {
            const int kb = kg * 16 + kk * 8;
            const float* ca = csA + kb * PC;
            const float* fb = fsB + kb * PF;
            unsigned b0[8], b1[8];
            #pragma unroll
            for (int nt = 0; nt < 8; nt++) {
                b0[nt] = fbits(fb[nt * 8]);
                b1[nt] = fbits(fb[4 * PF + nt * 8]);
            }
            #pragma unroll
            for (int mt = 0; mt < 2; mt++) {
                unsigned a0 = fbits_rn(ca[mt * 16]);
                unsigned a1 = fbits_rn(ca[mt * 16 + 8]);
                unsigned a2 = fbits_rn(ca[4 * PC + mt * 16]);
                unsigned a3 = fbits_rn(ca[4 * PC + mt * 16 + 8]);
                #pragma unroll
                for (int nt = 0; nt < 8; nt++)
                    MMA_TF32(acc[mt][nt], a0, a1, a2, a3, b0[nt], b1[nt]);
            }
        }

        // ---- unit boundary: two-pass fold + reduce ----
        if ((g & (SPU - 1)) == SPU - 1) {
            int u  = bid + (g >> 4) * GRID;
            int ks = u / NTILE;
            int m0 = (u - ks * NTILE) * MT;

            #pragma unroll
            for (int p = 0; p < 2; p++) {
                __syncthreads();
                if (kg == 0) {
                    int cr = mg * 16 + qid;
                    #pragma unroll
                    for (int nt = 0; nt < 8; nt++) {
                        int bc = nt * 8 + 2 * quad;
                        Ds[cr * PD + bc]           = acc[p][nt][0];
                        Ds[cr * PD + bc + 1]       = acc[p][nt][1];
                        Ds[(cr + 8) * PD + bc]     = acc[p][nt][2];
                        Ds[(cr + 8) * PD + bc + 1] = acc[p][nt][3];
                    }
                }
                __syncthreads();
                if (kg == 1) {
                    int cr = mg * 16 + qid;
                    #pragma unroll
                    for (int nt = 0; nt < 8; nt++) {
                        int bc = nt * 8 + 2 * quad;
                        Ds[cr * PD + bc]           += acc[p][nt][0];
                        Ds[cr * PD + bc + 1]       += acc[p][nt][1];
                        Ds[(cr + 8) * PD + bc]     += acc[p][nt][2];
                        Ds[(cr + 8) * PD + bc + 1] += acc[p][nt][3];
                    }
                }
                __syncthreads();
                // reduce this slab: thread (bb, mq) over 16 rows
                #pragma unroll 4
                for (int mm = 0; mm < 16; mm++) {
                    int m = m0 + mq * 32 + p * 16 + mm;
                    unsigned j = (unsigned)m / 3u;
                    int k = m - 3 * (int)j;
                    float t = Ds[(mq * 16 + mm) * PD + bb] * __ldg(argb + j);
                    if (k == 0) po0 += t;
                    else if (k == 1) po1 += t;
                    else po2 += t;
                }
            }
            __syncthreads();

            #pragma unroll
            for (int mt = 0; mt < 2; mt++)
                #pragma unroll
                for (int nt = 0; nt < 8; nt++)
                    #pragma unroll
                    for (int r = 0; r < 4; r++) acc[mt][nt][r] = 0.0f;
        }
    }

    // ---- final flush ----
    if (tid < 192) sout[tid] = 0.0f;
    __syncthreads();
    atomicAdd(&sout[bb * 3 + 0], po0);
    atomicAdd(&sout[bb * 3 + 1], po1);
    atomicAdd(&sout[bb * 3 + 2], po2);
    __syncthreads();
    if (tid < 192) atomicAdd(&out[tid], sout[tid]);
}

// ---------------------------------------------------------------------------
extern "C" void kernel_launch(void* const* d_in, const int* in_sizes, int n_in,
                              void* d_out, int out_size) {
    const float* func = (const float*)d_in[0];
    const float* arg  = (const float*)d_in[1];
    const float* cooc = (const float*)d_in[2];
    float* out = (float*)d_out;

    cudaFuncSetAttribute(cooc_mma, cudaFuncAttributeMaxDynamicSharedMemorySize, SMEM_DYN);

    prep_kernel<<<(V * NB) / 256, 256>>>(func, out);
    cooc_mma<<<GRID, 256, SMEM_DYN>>>(cooc, arg, out);
}